// round 1
// baseline (speedup 1.0000x reference)
#include <cuda_runtime.h>
#include <cstdint>

#define L2E 1.44269504088896340736f

// Scratch (no allocs allowed in kernel_launch)
__device__ float g_Wh[8*1024*128];   // 4 MB  [b][n][h*16+d]
__device__ float g_si[8*8*1024];     // scaled by log2e
__device__ float g_sj[8*8*1024];     // scaled by log2e
__device__ float g_att[8*1024*128];  // 4 MB

__device__ __forceinline__ unsigned long long pk2(float a, float b){
    unsigned long long r;
    asm("mov.b64 %0, {%1, %2};" : "=l"(r) : "f"(a), "f"(b));
    return r;
}
__device__ __forceinline__ void fma2(unsigned long long &d, unsigned long long a, unsigned long long b){
    asm("fma.rn.f32x2 %0, %1, %2, %0;" : "+l"(d) : "l"(a), "l"(b));
}
__device__ __forceinline__ float2 upk(unsigned long long v){
    float2 r;
    asm("mov.b64 {%0, %1}, %2;" : "=f"(r.x), "=f"(r.y) : "l"(v));
    return r;
}

// ---------------------------------------------------------------------------
// K1: Wh[b,n,h*16+d] = sum_i h[b,n,i] * W[h,i,d]; also s_i, s_j (x log2e)
// grid 512 x 128 threads; block = 16 rows
// ---------------------------------------------------------------------------
__global__ void __launch_bounds__(128) k1_wh(const float* __restrict__ h,
                                             const float* __restrict__ W,
                                             const float* __restrict__ a)
{
    __shared__ __align__(16) float hs[16][128];
    const int tid = threadIdx.x;
    const int gr0 = blockIdx.x * 16;
    {
        const float4* src = (const float4*)(h + gr0*128);
        float4* dst = (float4*)hs;
        #pragma unroll
        for (int q=0;q<4;q++) dst[q*128 + tid] = src[q*128 + tid];
    }
    __syncthreads();
    const int hh = tid >> 4, d = tid & 15;
    const float* wp = W + hh*2048 + d;  // W[h][i][d], stride 16 over i
    float acc[16];
    #pragma unroll
    for (int r=0;r<16;r++) acc[r] = 0.f;
    #pragma unroll 4
    for (int i4=0;i4<32;i4++){
        float w0 = __ldg(wp + (i4*4+0)*16);
        float w1 = __ldg(wp + (i4*4+1)*16);
        float w2 = __ldg(wp + (i4*4+2)*16);
        float w3 = __ldg(wp + (i4*4+3)*16);
        #pragma unroll
        for (int r=0;r<16;r++){
            float4 hv = *(const float4*)&hs[r][i4*4];
            acc[r] = fmaf(hv.x, w0, acc[r]);
            acc[r] = fmaf(hv.y, w1, acc[r]);
            acc[r] = fmaf(hv.z, w2, acc[r]);
            acc[r] = fmaf(hv.w, w3, acc[r]);
        }
    }
    const float asrc = __ldg(a + hh*32 + d);
    const float adst = __ldg(a + hh*32 + 16 + d);
    const int b  = gr0 >> 10;
    const int n0 = gr0 & 1023;
    #pragma unroll
    for (int r=0;r<16;r++){
        g_Wh[(gr0+r)*128 + tid] = acc[r];
        float p = acc[r]*asrc;
        float q = acc[r]*adst;
        #pragma unroll
        for (int o=8;o;o>>=1){
            p += __shfl_xor_sync(0xffffffffu, p, o);
            q += __shfl_xor_sync(0xffffffffu, q, o);
        }
        if (d == 0){
            g_si[(b*8+hh)*1024 + n0 + r] = p * L2E;
            g_sj[(b*8+hh)*1024 + n0 + r] = q * L2E;
        }
    }
}

// ---------------------------------------------------------------------------
// K2: fused masked-softmax attention (single pass, no max subtraction).
// grid (32 ntiles, 2 head-halves, 8 batches) x 128 threads.
// warp = one head, lane = one of 32 query rows; accum 16 dims/lane via f32x2.
// ---------------------------------------------------------------------------
__global__ void __launch_bounds__(128) k2_attn(const int* __restrict__ adj)
{
    __shared__ __align__(16) float Whs[64][64];   // 64 keys x 4 heads x 16 dims
    __shared__ __align__(16) float sjs[4][64];
    __shared__ unsigned int mbits[32][33];        // padded vs bank conflicts
    const int tid  = threadIdx.x;
    const int warp = tid >> 5, lane = tid & 31;
    const int nt = blockIdx.x, hb = blockIdx.y, b = blockIdx.z;
    const int h   = hb*4 + warp;
    const int row = nt*32 + lane;

    // pack adjacency bits for this block's 32 rows (1024 words / 4 warps)
    const int* mbase = adj + (b*1024 + nt*32)*1024;
    #pragma unroll 4
    for (int it=0; it<256; it++){
        int wd = it*4 + warp;
        int r = wd >> 5, k = wd & 31;
        unsigned v = __ballot_sync(0xffffffffu, mbase[r*1024 + k*32 + lane] != 0);
        if (lane == 0) mbits[r][k] = v;
    }

    const float siv = g_si[(b*8+h)*1024 + row];
    unsigned long long acc2[8];
    #pragma unroll
    for (int j=0;j<8;j++) acc2[j] = 0ull;
    float lsum = 0.f;

    for (int mt=0; mt<16; mt++){
        __syncthreads();
        {
            const float* srcbase = g_Wh + ((b<<10) + mt*64)*128 + hb*64;
            #pragma unroll
            for (int q=0;q<8;q++){
                int lin = q*128 + tid;
                int m = lin >> 4, c4 = lin & 15;
                ((float4*)Whs)[lin] = ((const float4*)(srcbase + m*128))[c4];
            }
            if (tid < 64){
                int hl = tid >> 4, c4 = tid & 15;
                ((float4*)sjs)[tid] =
                    ((const float4*)(g_sj + ((b*8 + hb*4 + hl)<<10) + mt*64))[c4];
            }
        }
        __syncthreads();
        #pragma unroll
        for (int k=0;k<2;k++){
            unsigned mw = mbits[lane][mt*2+k];
            #pragma unroll
            for (int j=0;j<32;j++){
                int m = k*32 + j;
                float u = siv + sjs[warp][m];
                float e = fmaxf(u, 0.2f*u);          // leaky relu (log2-scaled)
                float t = exp2f(e);
                float w = (mw & (1u<<j)) ? t : 0.f;
                lsum += w;
                unsigned long long ww = pk2(w, w);
                const ulonglong2* wv = (const ulonglong2*)&Whs[m][warp*16];
                ulonglong2 v0 = wv[0];
                ulonglong2 v1 = wv[1];
                fma2(acc2[0], v0.x, ww);
                fma2(acc2[1], v0.y, ww);
                fma2(acc2[2], v1.x, ww);
                fma2(acc2[3], v1.y, ww);
                ulonglong2 v2 = wv[2];
                ulonglong2 v3 = wv[3];
                fma2(acc2[4], v2.x, ww);
                fma2(acc2[5], v2.y, ww);
                fma2(acc2[6], v3.x, ww);
                fma2(acc2[7], v3.y, ww);
            }
        }
    }
    float inv = (lsum > 0.f) ? __fdividef(1.f, lsum) : 0.f;
    float* outp = g_att + ((b<<10) + row)*128 + h*16;
    #pragma unroll
    for (int j=0;j<4;j++){
        float2 p0 = upk(acc2[j*2]);
        float2 p1 = upk(acc2[j*2+1]);
        float4 o;
        o.x = p0.x*inv; o.y = p0.y*inv; o.z = p1.x*inv; o.w = p1.y*inv;
        ((float4*)outp)[j] = o;
    }
}

// ---------------------------------------------------------------------------
// K3: hc = LN1(att + h); out = LN2(hc + relu(hc@w1+b1)@w2 + b2)
// grid 512 x 256 threads; block = 16 rows
// ---------------------------------------------------------------------------
__global__ void __launch_bounds__(256) k3_ffn(
    const float* __restrict__ h,
    const float* __restrict__ ln1g, const float* __restrict__ ln1b,
    const float* __restrict__ w1,   const float* __restrict__ b1,
    const float* __restrict__ w2,   const float* __restrict__ b2,
    const float* __restrict__ ln2g, const float* __restrict__ ln2b,
    float* __restrict__ out)
{
    __shared__ __align__(16) float hcs[16][128];
    __shared__ __align__(16) float mids[16][256];
    const int tid = threadIdx.x;
    const int gr0 = blockIdx.x * 16;
    const int r = tid >> 4, l16 = tid & 15;
    const int gr = gr0 + r;

    // Stage 1: LN1(att + h) -> hcs
    float x[8];
    {
        const float4* hp = (const float4*)(h + gr*128 + l16*8);
        const float4* ap = (const float4*)(g_att + gr*128 + l16*8);
        float4 h0 = hp[0], h1 = hp[1];
        float4 a0 = ap[0], a1 = ap[1];
        x[0]=h0.x+a0.x; x[1]=h0.y+a0.y; x[2]=h0.z+a0.z; x[3]=h0.w+a0.w;
        x[4]=h1.x+a1.x; x[5]=h1.y+a1.y; x[6]=h1.z+a1.z; x[7]=h1.w+a1.w;
    }
    float s=0.f, sq=0.f;
    #pragma unroll
    for (int i=0;i<8;i++){ s += x[i]; sq = fmaf(x[i],x[i],sq); }
    #pragma unroll
    for (int o=8;o;o>>=1){
        s  += __shfl_xor_sync(0xffffffffu, s,  o);
        sq += __shfl_xor_sync(0xffffffffu, sq, o);
    }
    float mu   = s * 0.0078125f;
    float var  = fmaf(sq, 0.0078125f, -mu*mu);
    float rstd = rsqrtf(var + 1e-5f);
    #pragma unroll
    for (int i=0;i<8;i++){
        int c = l16*8 + i;
        hcs[r][c] = (x[i]-mu)*rstd*__ldg(ln1g+c) + __ldg(ln1b+c);
    }
    __syncthreads();

    // Stage 2: mids = relu(hc @ w1 + b1)   (w1 hoisted over 16 rows)
    {
        float acc[16];
        #pragma unroll
        for (int rr=0;rr<16;rr++) acc[rr]=0.f;
        for (int i4=0;i4<32;i4++){
            float wv0 = __ldg(w1 + (i4*4+0)*256 + tid);
            float wv1 = __ldg(w1 + (i4*4+1)*256 + tid);
            float wv2 = __ldg(w1 + (i4*4+2)*256 + tid);
            float wv3 = __ldg(w1 + (i4*4+3)*256 + tid);
            #pragma unroll
            for (int rr=0;rr<16;rr++){
                float4 hv = *(const float4*)&hcs[rr][i4*4];
                acc[rr] = fmaf(hv.x,wv0,acc[rr]);
                acc[rr] = fmaf(hv.y,wv1,acc[rr]);
                acc[rr] = fmaf(hv.z,wv2,acc[rr]);
                acc[rr] = fmaf(hv.w,wv3,acc[rr]);
            }
        }
        float bb = __ldg(b1 + tid);
        #pragma unroll
        for (int rr=0;rr<16;rr++) mids[rr][tid] = fmaxf(acc[rr]+bb, 0.f);
    }
    __syncthreads();

    // Stage 3: z = hc + mid @ w2 + b2  (in place in hcs)
    {
        const int c = tid & 127, half = tid >> 7;
        float acc[8];
        #pragma unroll
        for (int rr=0;rr<8;rr++) acc[rr]=0.f;
        for (int k4=0;k4<64;k4++){
            float wv0 = __ldg(w2 + (k4*4+0)*128 + c);
            float wv1 = __ldg(w2 + (k4*4+1)*128 + c);
            float wv2 = __ldg(w2 + (k4*4+2)*128 + c);
            float wv3 = __ldg(w2 + (k4*4+3)*128 + c);
            #pragma unroll
            for (int rr=0;rr<8;rr++){
                float4 mv = *(const float4*)&mids[half*8+rr][k4*4];
                acc[rr] = fmaf(mv.x,wv0,acc[rr]);
                acc[rr] = fmaf(mv.y,wv1,acc[rr]);
                acc[rr] = fmaf(mv.z,wv2,acc[rr]);
                acc[rr] = fmaf(mv.w,wv3,acc[rr]);
            }
        }
        float bb = __ldg(b2 + c);
        #pragma unroll
        for (int rr=0;rr<8;rr++){
            hcs[half*8+rr][c] += acc[rr] + bb;
        }
    }
    __syncthreads();

    // Stage 4: LN2 -> out
    float z[8];
    #pragma unroll
    for (int i=0;i<8;i++) z[i] = hcs[r][l16*8+i];
    float s2=0.f, sq2=0.f;
    #pragma unroll
    for (int i=0;i<8;i++){ s2 += z[i]; sq2 = fmaf(z[i],z[i],sq2); }
    #pragma unroll
    for (int o=8;o;o>>=1){
        s2  += __shfl_xor_sync(0xffffffffu, s2,  o);
        sq2 += __shfl_xor_sync(0xffffffffu, sq2, o);
    }
    float mu2   = s2 * 0.0078125f;
    float var2  = fmaf(sq2, 0.0078125f, -mu2*mu2);
    float rstd2 = rsqrtf(var2 + 1e-5f);
    float t[8];
    #pragma unroll
    for (int i=0;i<8;i++){
        int c = l16*8+i;
        t[i] = (z[i]-mu2)*rstd2*__ldg(ln2g+c) + __ldg(ln2b+c);
    }
    float* op = out + gr*128 + l16*8;
    ((float4*)op)[0] = make_float4(t[0],t[1],t[2],t[3]);
    ((float4*)op)[1] = make_float4(t[4],t[5],t[6],t[7]);
}

// ---------------------------------------------------------------------------
extern "C" void kernel_launch(void* const* d_in, const int* in_sizes, int n_in,
                              void* d_out, int out_size)
{
    const float* h    = (const float*)d_in[0];
    const int*   adj  = (const int*  )d_in[1];
    const float* W    = (const float*)d_in[2];
    const float* a    = (const float*)d_in[3];
    const float* ln1g = (const float*)d_in[4];
    const float* ln1b = (const float*)d_in[5];
    const float* w1   = (const float*)d_in[6];
    const float* b1   = (const float*)d_in[7];
    const float* w2   = (const float*)d_in[8];
    const float* b2   = (const float*)d_in[9];
    const float* ln2g = (const float*)d_in[10];
    const float* ln2b = (const float*)d_in[11];
    float* out = (float*)d_out;

    k1_wh<<<512, 128>>>(h, W, a);
    k2_attn<<<dim3(32, 2, 8), 128>>>(adj);
    k3_ffn<<<512, 256>>>(h, ln1g, ln1b, w1, b1, w2, b2, ln2g, ln2b, out);
}

// round 2
// speedup vs baseline: 1.1274x; 1.1274x over previous
#include <cuda_runtime.h>
#include <cstdint>

#define L2E 1.44269504088896340736f

// Scratch (no allocs allowed in kernel_launch)
__device__ float  g_Wh[8*1024*128];     // 4 MB  [b][n][h*16+d]
__device__ float4 g_p[8*8*1024];        // per (b,h,row): p1=2^(L2E*si), p2=2^(0.2*L2E*si), thr=2^(-L2E*si)
__device__ float2 g_q[8*8*1024];        // per (b,h,key): q1=2^(L2E*sj), q2=2^(0.2*L2E*sj)
__device__ unsigned g_mb[8*1024*32];    // packed adjacency bits
__device__ float  g_att[8*1024*128];    // 4 MB

__device__ __forceinline__ unsigned long long pk2(float a, float b){
    unsigned long long r;
    asm("mov.b64 %0, {%1, %2};" : "=l"(r) : "f"(a), "f"(b));
    return r;
}
__device__ __forceinline__ void fma2(unsigned long long &d, unsigned long long a, unsigned long long b){
    asm("fma.rn.f32x2 %0, %1, %2, %0;" : "+l"(d) : "l"(a), "l"(b));
}
__device__ __forceinline__ float2 upk(unsigned long long v){
    float2 r;
    asm("mov.b64 {%0, %1}, %2;" : "=f"(r.x), "=f"(r.y) : "l"(v));
    return r;
}

// ---------------------------------------------------------------------------
// K0: pack adjacency into bitmask words. One warp per row.
// ---------------------------------------------------------------------------
__global__ void __launch_bounds__(256) k0_pack(const int* __restrict__ adj)
{
    const int gw   = blockIdx.x * 8 + (threadIdx.x >> 5);  // 0..8191 (b*1024+row)
    const int lane = threadIdx.x & 31;
    const int* rp  = adj + (size_t)gw * 1024;
    unsigned* op   = g_mb + gw * 32;
    #pragma unroll
    for (int w = 0; w < 32; w++){
        unsigned v = __ballot_sync(0xffffffffu, rp[w*32 + lane] != 0);
        if (lane == 0) op[w] = v;
    }
}

// ---------------------------------------------------------------------------
// K1: Wh = h@W; also per-row/per-key exp tables for factorized leaky-softmax.
// grid 512 x 128 threads; block = 16 rows
// ---------------------------------------------------------------------------
__global__ void __launch_bounds__(128) k1_wh(const float* __restrict__ h,
                                             const float* __restrict__ W,
                                             const float* __restrict__ a)
{
    __shared__ __align__(16) float hs[16][128];
    __shared__ __align__(16) float ps[16][128];
    __shared__ __align__(16) float qs[16][128];
    const int tid = threadIdx.x;
    const int gr0 = blockIdx.x * 16;
    {
        const float4* src = (const float4*)(h + gr0*128);
        float4* dst = (float4*)hs;
        #pragma unroll
        for (int q=0;q<4;q++) dst[q*128 + tid] = src[q*128 + tid];
    }
    __syncthreads();
    const int hh = tid >> 4, d = tid & 15;
    const float* wp = W + hh*2048 + d;  // W[h][i][d], stride 16 over i
    float acc[16];
    #pragma unroll
    for (int r=0;r<16;r++) acc[r] = 0.f;
    #pragma unroll 4
    for (int i4=0;i4<32;i4++){
        float w0 = __ldg(wp + (i4*4+0)*16);
        float w1 = __ldg(wp + (i4*4+1)*16);
        float w2 = __ldg(wp + (i4*4+2)*16);
        float w3 = __ldg(wp + (i4*4+3)*16);
        #pragma unroll
        for (int r=0;r<16;r++){
            float4 hv = *(const float4*)&hs[r][i4*4];
            acc[r] = fmaf(hv.x, w0, acc[r]);
            acc[r] = fmaf(hv.y, w1, acc[r]);
            acc[r] = fmaf(hv.z, w2, acc[r]);
            acc[r] = fmaf(hv.w, w3, acc[r]);
        }
    }
    const float asrc = __ldg(a + hh*32 + d);
    const float adst = __ldg(a + hh*32 + 16 + d);
    #pragma unroll
    for (int r=0;r<16;r++){
        g_Wh[(gr0+r)*128 + tid] = acc[r];
        ps[r][tid] = acc[r]*asrc;
        qs[r][tid] = acc[r]*adst;
    }
    __syncthreads();

    // reduce 16 dims per (row, head); thread = (rr, hh2)
    const int rr = tid >> 3, hh2 = tid & 7;
    const float4* pp = (const float4*)&ps[rr][hh2*16];
    const float4* qq = (const float4*)&qs[rr][hh2*16];
    float4 a0=pp[0], a1=pp[1], a2=pp[2], a3=pp[3];
    float4 b0=qq[0], b1=qq[1], b2=qq[2], b3=qq[3];
    float si = ((a0.x+a0.y)+(a0.z+a0.w)) + ((a1.x+a1.y)+(a1.z+a1.w))
             + ((a2.x+a2.y)+(a2.z+a2.w)) + ((a3.x+a3.y)+(a3.z+a3.w));
    float sj = ((b0.x+b0.y)+(b0.z+b0.w)) + ((b1.x+b1.y)+(b1.z+b1.w))
             + ((b2.x+b2.y)+(b2.z+b2.w)) + ((b3.x+b3.y)+(b3.z+b3.w));
    si *= L2E; sj *= L2E;
    const int b  = gr0 >> 10;
    const int n0 = gr0 & 1023;
    const int idx = (b*8 + hh2)*1024 + n0 + rr;
    g_p[idx] = make_float4(exp2f(si), exp2f(0.2f*si), exp2f(-si), 0.f);
    g_q[idx] = make_float2(exp2f(sj), exp2f(0.2f*sj));
}

// ---------------------------------------------------------------------------
// K2: fused masked-softmax attention. MUFU-free inner loop.
// grid (32 ntiles, 2 head-halves, 8 batches) x 256 threads.
// warps 0-3: heads, keys [0,512); warps 4-7: same heads, keys [512,1024).
// lane = query row; 16 dims/lane via f32x2. Partials combined via smem.
// ---------------------------------------------------------------------------
__global__ void __launch_bounds__(256) k2_attn()
{
    __shared__ __align__(16) float Whs[128][64];   // 128 keys x 4 heads x 16 dims
    __shared__ __align__(16) float2 qt[4][128];    // (q1,q2) per head per key
    __shared__ unsigned mbits[32][33];             // padded vs bank conflicts
    const int tid  = threadIdx.x;
    const int warp = tid >> 5, lane = tid & 31;
    const int hw = warp & 3, grp = warp >> 2;
    const int nt = blockIdx.x, hb = blockIdx.y, b = blockIdx.z;
    const int h   = hb*4 + hw;
    const int row = nt*32 + lane;

    // load packed mask bits for this block's 32 rows
    {
        const unsigned* src = g_mb + (b*1024 + nt*32)*32;
        #pragma unroll
        for (int q=0;q<4;q++){
            int lin = q*256 + tid;
            mbits[lin>>5][lin&31] = src[lin];
        }
    }

    const float4 pv = g_p[(b*8+h)*1024 + row];
    const float p1 = pv.x, p2 = pv.y, thr = pv.z;

    unsigned long long acc2[8];
    #pragma unroll
    for (int j=0;j<8;j++) acc2[j] = 0ull;
    float lsum = 0.f;

    const int bhq = b*8 + hb*4;
    for (int mt=0; mt<8; mt++){
        __syncthreads();
        {
            const float* base = g_Wh + ((size_t)(b<<10))*128 + hb*64;
            #pragma unroll
            for (int q=0;q<8;q++){
                int lin = q*256 + tid;
                int r = lin >> 4, c4 = lin & 15;
                int key = (r < 64) ? (mt*64 + r) : (448 + mt*64 + r);
                ((float4*)Whs)[lin] = ((const float4*)(base + key*128))[c4];
            }
            #pragma unroll
            for (int q=0;q<2;q++){
                int lin = q*256 + tid;
                int hl = lin >> 7, k128 = lin & 127;
                int key = (k128 < 64) ? (mt*64 + k128) : (448 + mt*64 + k128);
                qt[hl][k128] = g_q[(bhq+hl)*1024 + key];
            }
        }
        __syncthreads();
        const float2* qp = &qt[hw][grp*64];
        const float*  wb = &Whs[grp*64][0] + hw*16;
        #pragma unroll
        for (int k=0;k<2;k++){
            unsigned mw = mbits[lane][grp*16 + mt*2 + k];
            #pragma unroll
            for (int j=0;j<32;j++){
                int m = k*32 + j;
                float2 q = qp[m];
                bool c = (q.x >= thr);
                float pp2 = c ? p1 : p2;
                float qq2 = c ? q.x : q.y;
                float t = pp2 * qq2;
                float w = (mw & (1u<<j)) ? t : 0.f;
                lsum += w;
                unsigned long long ww = pk2(w, w);
                const ulonglong2* wv = (const ulonglong2*)(wb + m*64);
                ulonglong2 v0 = wv[0];
                ulonglong2 v1 = wv[1];
                fma2(acc2[0], v0.x, ww);
                fma2(acc2[1], v0.y, ww);
                fma2(acc2[2], v1.x, ww);
                fma2(acc2[3], v1.y, ww);
                ulonglong2 v2 = wv[2];
                ulonglong2 v3 = wv[3];
                fma2(acc2[4], v2.x, ww);
                fma2(acc2[5], v2.y, ww);
                fma2(acc2[6], v3.x, ww);
                fma2(acc2[7], v3.y, ww);
            }
        }
    }

    // combine the two key-half groups through smem (alias onto Whs)
    __syncthreads();
    unsigned long long (*red)[32][9] = (unsigned long long(*)[32][9])Whs;
    if (grp == 1){
        #pragma unroll
        for (int j=0;j<8;j++) red[hw][lane][j] = acc2[j];
        red[hw][lane][8] = pk2(lsum, 0.f);
    }
    __syncthreads();
    if (grp == 0){
        lsum += upk(red[hw][lane][8]).x;
        float inv = (lsum > 0.f) ? __fdividef(1.f, lsum) : 0.f;
        float* outp = g_att + ((size_t)(b<<10) + row)*128 + h*16;
        #pragma unroll
        for (int j=0;j<4;j++){
            float2 pa0 = upk(acc2[j*2]);
            float2 pa1 = upk(acc2[j*2+1]);
            float2 pb0 = upk(red[hw][lane][j*2]);
            float2 pb1 = upk(red[hw][lane][j*2+1]);
            float4 o;
            o.x = (pa0.x+pb0.x)*inv; o.y = (pa0.y+pb0.y)*inv;
            o.z = (pa1.x+pb1.x)*inv; o.w = (pa1.y+pb1.y)*inv;
            ((float4*)outp)[j] = o;
        }
    }
}

// ---------------------------------------------------------------------------
// K3: hc = LN1(att + h); out = LN2(hc + relu(hc@w1+b1)@w2 + b2)
// grid 512 x 256 threads; block = 16 rows
// ---------------------------------------------------------------------------
__global__ void __launch_bounds__(256) k3_ffn(
    const float* __restrict__ h,
    const float* __restrict__ ln1g, const float* __restrict__ ln1b,
    const float* __restrict__ w1,   const float* __restrict__ b1,
    const float* __restrict__ w2,   const float* __restrict__ b2,
    const float* __restrict__ ln2g, const float* __restrict__ ln2b,
    float* __restrict__ out)
{
    __shared__ __align__(16) float hcs[16][128];
    __shared__ __align__(16) float mids[16][256];
    const int tid = threadIdx.x;
    const int gr0 = blockIdx.x * 16;
    const int r = tid >> 4, l16 = tid & 15;
    const int gr = gr0 + r;

    // Stage 1: LN1(att + h) -> hcs
    float x[8];
    {
        const float4* hp = (const float4*)(h + gr*128 + l16*8);
        const float4* ap = (const float4*)(g_att + gr*128 + l16*8);
        float4 h0 = hp[0], h1 = hp[1];
        float4 a0 = ap[0], a1 = ap[1];
        x[0]=h0.x+a0.x; x[1]=h0.y+a0.y; x[2]=h0.z+a0.z; x[3]=h0.w+a0.w;
        x[4]=h1.x+a1.x; x[5]=h1.y+a1.y; x[6]=h1.z+a1.z; x[7]=h1.w+a1.w;
    }
    float s=0.f, sq=0.f;
    #pragma unroll
    for (int i=0;i<8;i++){ s += x[i]; sq = fmaf(x[i],x[i],sq); }
    #pragma unroll
    for (int o=8;o;o>>=1){
        s  += __shfl_xor_sync(0xffffffffu, s,  o);
        sq += __shfl_xor_sync(0xffffffffu, sq, o);
    }
    float mu   = s * 0.0078125f;
    float var  = fmaf(sq, 0.0078125f, -mu*mu);
    float rstd = rsqrtf(var + 1e-5f);
    #pragma unroll
    for (int i=0;i<8;i++){
        int c = l16*8 + i;
        hcs[r][c] = (x[i]-mu)*rstd*__ldg(ln1g+c) + __ldg(ln1b+c);
    }
    __syncthreads();

    // Stage 2: mids = relu(hc @ w1 + b1)
    {
        float acc[16];
        #pragma unroll
        for (int rr=0;rr<16;rr++) acc[rr]=0.f;
        for (int i4=0;i4<32;i4++){
            float wv0 = __ldg(w1 + (i4*4+0)*256 + tid);
            float wv1 = __ldg(w1 + (i4*4+1)*256 + tid);
            float wv2 = __ldg(w1 + (i4*4+2)*256 + tid);
            float wv3 = __ldg(w1 + (i4*4+3)*256 + tid);
            #pragma unroll
            for (int rr=0;rr<16;rr++){
                float4 hv = *(const float4*)&hcs[rr][i4*4];
                acc[rr] = fmaf(hv.x,wv0,acc[rr]);
                acc[rr] = fmaf(hv.y,wv1,acc[rr]);
                acc[rr] = fmaf(hv.z,wv2,acc[rr]);
                acc[rr] = fmaf(hv.w,wv3,acc[rr]);
            }
        }
        float bb = __ldg(b1 + tid);
        #pragma unroll
        for (int rr=0;rr<16;rr++) mids[rr][tid] = fmaxf(acc[rr]+bb, 0.f);
    }
    __syncthreads();

    // Stage 3: z = hc + mid @ w2 + b2  (in place in hcs)
    {
        const int c = tid & 127, half = tid >> 7;
        float acc[8];
        #pragma unroll
        for (int rr=0;rr<8;rr++) acc[rr]=0.f;
        for (int k4=0;k4<64;k4++){
            float wv0 = __ldg(w2 + (k4*4+0)*128 + c);
            float wv1 = __ldg(w2 + (k4*4+1)*128 + c);
            float wv2 = __ldg(w2 + (k4*4+2)*128 + c);
            float wv3 = __ldg(w2 + (k4*4+3)*128 + c);
            #pragma unroll
            for (int rr=0;rr<8;rr++){
                float4 mv = *(const float4*)&mids[half*8+rr][k4*4];
                acc[rr] = fmaf(mv.x,wv0,acc[rr]);
                acc[rr] = fmaf(mv.y,wv1,acc[rr]);
                acc[rr] = fmaf(mv.z,wv2,acc[rr]);
                acc[rr] = fmaf(mv.w,wv3,acc[rr]);
            }
        }
        float bb = __ldg(b2 + c);
        #pragma unroll
        for (int rr=0;rr<8;rr++){
            hcs[half*8+rr][c] += acc[rr] + bb;
        }
    }
    __syncthreads();

    // Stage 4: LN2 -> out
    float z[8];
    #pragma unroll
    for (int i=0;i<8;i++) z[i] = hcs[r][l16*8+i];
    float s2=0.f, sq2=0.f;
    #pragma unroll
    for (int i=0;i<8;i++){ s2 += z[i]; sq2 = fmaf(z[i],z[i],sq2); }
    #pragma unroll
    for (int o=8;o;o>>=1){
        s2  += __shfl_xor_sync(0xffffffffu, s2,  o);
        sq2 += __shfl_xor_sync(0xffffffffu, sq2, o);
    }
    float mu2   = s2 * 0.0078125f;
    float var2  = fmaf(sq2, 0.0078125f, -mu2*mu2);
    float rstd2 = rsqrtf(var2 + 1e-5f);
    float t[8];
    #pragma unroll
    for (int i=0;i<8;i++){
        int c = l16*8+i;
        t[i] = (z[i]-mu2)*rstd2*__ldg(ln2g+c) + __ldg(ln2b+c);
    }
    float* op = out + gr*128 + l16*8;
    ((float4*)op)[0] = make_float4(t[0],t[1],t[2],t[3]);
    ((float4*)op)[1] = make_float4(t[4],t[5],t[6],t[7]);
}

// ---------------------------------------------------------------------------
extern "C" void kernel_launch(void* const* d_in, const int* in_sizes, int n_in,
                              void* d_out, int out_size)
{
    const float* h    = (const float*)d_in[0];
    const int*   adj  = (const int*  )d_in[1];
    const float* W    = (const float*)d_in[2];
    const float* a    = (const float*)d_in[3];
    const float* ln1g = (const float*)d_in[4];
    const float* ln1b = (const float*)d_in[5];
    const float* w1   = (const float*)d_in[6];
    const float* b1   = (const float*)d_in[7];
    const float* w2   = (const float*)d_in[8];
    const float* b2   = (const float*)d_in[9];
    const float* ln2g = (const float*)d_in[10];
    const float* ln2b = (const float*)d_in[11];
    float* out = (float*)d_out;

    k0_pack<<<1024, 256>>>(adj);
    k1_wh<<<512, 128>>>(h, W, a);
    k2_attn<<<dim3(32, 2, 8), 256>>>();
    k3_ffn<<<512, 256>>>(h, ln1g, ln1b, w1, b1, w2, b2, ln2g, ln2b, out);
}